// round 14
// baseline (speedup 1.0000x reference)
#include <cuda_runtime.h>
#include <math.h>

#define Qn 2048
#define Dn 256
#define Nn 32768
#define Hn 8
#define STn 64
#define DINn 512
#define CONVn 640
#define NPROJn 1160
#define HIDn 1024
#define KCn 4
#define Ln 2048

// ---------------- scratch (device globals) ----------------
__device__ float g_q[Qn*Dn];
__device__ float g_fbar[Qn*Dn];
__device__ float g_vbar[Qn*Dn];
__device__ float g_wtmp[Qn*Dn];
__device__ float g_wo[Qn*Dn];
__device__ float g_x[Qn*Dn];
__device__ float g_xn[Qn*Dn];
__device__ float g_xs[2*Qn*Dn];
__device__ float g_proj[2*Qn*NPROJn];
__device__ float g_xbc[2*Qn*CONVn];
__device__ float g_dt[2*Qn*Hn];
__device__ float g_dAr[2*Qn*Hn];
__device__ float g_ys[2*Qn*DINn];
__device__ float g_gated[2*Qn*DINn];
__device__ float g_mo[2*Qn*Dn];
__device__ float g_ffnh[Qn*HIDn];
__device__ float g_ffno[Qn*Dn];
__device__ float4 g_sp4[Nn];
__device__ int g_idx[Qn*8];
__device__ int g_inv[2*Qn];

// ---------------- helpers ----------------
template<int NT>
__device__ __forceinline__ float blockSum(float v) {
    __shared__ float sm[NT/32];
    unsigned m = 0xffffffffu;
    v += __shfl_xor_sync(m, v, 16);
    v += __shfl_xor_sync(m, v, 8);
    v += __shfl_xor_sync(m, v, 4);
    v += __shfl_xor_sync(m, v, 2);
    v += __shfl_xor_sync(m, v, 1);
    int w = threadIdx.x >> 5;
    if ((threadIdx.x & 31) == 0) sm[w] = v;
    __syncthreads();
    float t = sm[0];
#pragma unroll
    for (int k = 1; k < NT/32; k++) t += sm[k];
    __syncthreads();
    return t;
}

// ---------------- GEMM: C = act(A[M,K] @ W[N,K]^T + bias) ----------------
// BM=BN=64, BK=16, 256 threads, 4x4 microtile. M%64==0, K%16==0 guaranteed.
__global__ __launch_bounds__(256) void gemm_kernel(
    const float* __restrict__ A, const float* __restrict__ W,
    const float* __restrict__ bias, float* __restrict__ C,
    int M, int N, int K, int act)
{
    __shared__ float As[16][68];
    __shared__ float Ws[16][68];
    int tx = threadIdx.x, ty = threadIdx.y;
    int tid = ty * 16 + tx;
    int m0 = blockIdx.y * 64;
    int n0 = blockIdx.x * 64;
    int lr = tid >> 2;
    int lc = (tid & 3) * 4;

    float acc[4][4];
#pragma unroll
    for (int i = 0; i < 4; i++)
#pragma unroll
        for (int j = 0; j < 4; j++) acc[i][j] = 0.f;

    for (int k0 = 0; k0 < K; k0 += 16) {
        float4 av = *(const float4*)&A[(size_t)(m0 + lr) * K + k0 + lc];
        As[lc+0][lr] = av.x; As[lc+1][lr] = av.y; As[lc+2][lr] = av.z; As[lc+3][lr] = av.w;
        int wr = n0 + lr;
        float4 wv = make_float4(0.f, 0.f, 0.f, 0.f);
        if (wr < N) wv = *(const float4*)&W[(size_t)wr * K + k0 + lc];
        Ws[lc+0][lr] = wv.x; Ws[lc+1][lr] = wv.y; Ws[lc+2][lr] = wv.z; Ws[lc+3][lr] = wv.w;
        __syncthreads();
#pragma unroll
        for (int k = 0; k < 16; k++) {
            float4 a4 = *(const float4*)&As[k][ty * 4];
            float4 b4 = *(const float4*)&Ws[k][tx * 4];
            float ar[4] = {a4.x, a4.y, a4.z, a4.w};
            float br[4] = {b4.x, b4.y, b4.z, b4.w};
#pragma unroll
            for (int i = 0; i < 4; i++)
#pragma unroll
                for (int j = 0; j < 4; j++)
                    acc[i][j] += ar[i] * br[j];
        }
        __syncthreads();
    }
#pragma unroll
    for (int i = 0; i < 4; i++) {
        int mrow = m0 + ty * 4 + i;
#pragma unroll
        for (int j = 0; j < 4; j++) {
            int ncol = n0 + tx * 4 + j;
            if (ncol < N) {
                float v = acc[i][j];
                if (bias) v += bias[ncol];
                if (act == 1) v = 0.5f * v * (1.f + erff(v * 0.7071067811865475f));
                C[(size_t)mrow * N + ncol] = v;
            }
        }
    }
}

// ---------------- pack sp coords ----------------
__global__ void pack_sp_kernel(const float* __restrict__ sp) {
    int i = blockIdx.x * blockDim.x + threadIdx.x;
    if (i < Nn) {
        float x = sp[3*i], y = sp[3*i+1], z = sp[3*i+2];
        g_sp4[i] = make_float4(x, y, z, x*x + y*y + z*z);
    }
}

// ---------------- KNN ----------------
__device__ __forceinline__ bool knn_less(float da, int ia, float db, int ib) {
    return (da < db) || (da == db && ia < ib);
}

__global__ __launch_bounds__(256) void knn_kernel(const float* __restrict__ qpos) {
    __shared__ float4 tile[2048];
    int tid = threadIdx.x;
    int ql = tid & 15;
    int lg = tid >> 4;
    int q = blockIdx.x * 16 + ql;
    float qx = qpos[3*q], qy = qpos[3*q+1], qz = qpos[3*q+2];

    float bd[8]; int bi[8];
#pragma unroll
    for (int j = 0; j < 8; j++) { bd[j] = 3.4e38f; bi[j] = 0x7fffffff; }

    for (int tb = 0; tb < Nn; tb += 2048) {
        __syncthreads();
        for (int i = tid; i < 2048; i += 256) tile[i] = g_sp4[tb + i];
        __syncthreads();
        for (int i = lg; i < 2048; i += 16) {
            float4 s = tile[i];
            float d = s.w - 2.f * (qx*s.x + qy*s.y + qz*s.z);
            int n = tb + i;
            if (knn_less(d, n, bd[7], bi[7])) {
                float cd = d; int ci = n;
#pragma unroll
                for (int p = 0; p < 8; p++) {
                    if (knn_less(cd, ci, bd[p], bi[p])) {
                        float tf = bd[p]; bd[p] = cd; cd = tf;
                        int ti = bi[p]; bi[p] = ci; ci = ti;
                    }
                }
            }
        }
    }
    __syncthreads();
    float* sd = (float*)tile;
    int* si = (int*)(sd + 2048);
#pragma unroll
    for (int j = 0; j < 8; j++) { sd[tid*8+j] = bd[j]; si[tid*8+j] = bi[j]; }
    __syncthreads();
    for (int st = 8; st >= 1; st >>= 1) {
        if (lg < st) {
            int op = tid + st * 16;
#pragma unroll
            for (int j = 0; j < 8; j++) {
                float cd = sd[op*8+j]; int ci = si[op*8+j];
                if (knn_less(cd, ci, bd[7], bi[7])) {
#pragma unroll
                    for (int p = 0; p < 8; p++) {
                        if (knn_less(cd, ci, bd[p], bi[p])) {
                            float tf = bd[p]; bd[p] = cd; cd = tf;
                            int ti = bi[p]; bi[p] = ci; ci = ti;
                        }
                    }
                }
            }
#pragma unroll
            for (int j = 0; j < 8; j++) { sd[tid*8+j] = bd[j]; si[tid*8+j] = bi[j]; }
        }
        __syncthreads();
    }
    if (lg == 0) {
#pragma unroll
        for (int j = 0; j < 8; j++) g_idx[q*8+j] = bi[j];
    }
}

// ---------------- kw softmax + weighted feature mix ----------------
__global__ __launch_bounds__(256) void kwfbar_kernel(
    const float* __restrict__ wk, const float* __restrict__ wb,
    const float* __restrict__ feats)
{
    int q = blockIdx.x;
    __shared__ float sc[8];
    int w = threadIdx.x >> 5, lane = threadIdx.x & 31;
    const float* qr = g_q + (size_t)q * Dn;
    float s = 0.f;
    for (int d = lane; d < Dn; d += 32) s += qr[d] * wk[w*Dn + d];
    unsigned m = 0xffffffffu;
    s += __shfl_xor_sync(m, s, 16); s += __shfl_xor_sync(m, s, 8);
    s += __shfl_xor_sync(m, s, 4);  s += __shfl_xor_sync(m, s, 2);
    s += __shfl_xor_sync(m, s, 1);
    if (lane == 0) sc[w] = s + wb[w];
    __syncthreads();
    float mx = sc[0];
#pragma unroll
    for (int k = 1; k < 8; k++) mx = fmaxf(mx, sc[k]);
    float kwv[8]; float ssum = 0.f;
#pragma unroll
    for (int k = 0; k < 8; k++) { kwv[k] = expf(sc[k] - mx); ssum += kwv[k]; }
    float inv = 1.f / ssum;
    int d = threadIdx.x;
    float acc = 0.f;
#pragma unroll
    for (int k = 0; k < 8; k++) {
        int id = g_idx[q*8 + k];
        acc += kwv[k] * inv * feats[(size_t)id * Dn + d];
    }
    g_fbar[(size_t)q * Dn + d] = acc;
}

__global__ void mul_kernel() {
    int i = blockIdx.x * blockDim.x + threadIdx.x;
    if (i < Qn*Dn) g_wtmp[i] = g_q[i] * g_vbar[i];
}

// ---------------- LayerNorm: dst = LN(a [+ b]) ----------------
__global__ __launch_bounds__(256) void ln_kernel(
    float* __restrict__ dst, const float* __restrict__ a, const float* __restrict__ b)
{
    int row = blockIdx.x, d = threadIdx.x;
    float v = a[(size_t)row*Dn + d];
    if (b) v += b[(size_t)row*Dn + d];
    float mean = blockSum<256>(v) * (1.f/Dn);
    float c = v - mean;
    float var = blockSum<256>(c*c) * (1.f/Dn);
    dst[(size_t)row*Dn + d] = c * rsqrtf(var + 1e-5f);
}

__global__ void gather_kernel(const int* __restrict__ order) {
    int r = blockIdx.x;
    int src = order[r];
    g_xs[(size_t)r*Dn + threadIdx.x] = g_xn[(size_t)src*Dn + threadIdx.x];
}

__global__ void inv_kernel(const int* __restrict__ order) {
    int i = blockIdx.x * blockDim.x + threadIdx.x;
    if (i < 2*Qn) {
        int p = i >> 11, j = i & 2047;
        g_inv[p*Qn + order[i]] = j;
    }
}

// ---------------- causal depthwise conv(4) + silu ----------------
__global__ void conv_kernel(const float* __restrict__ Wc, const float* __restrict__ bc) {
    int t = blockIdx.x, b = blockIdx.y, c = threadIdx.x;
    size_t rbase = (size_t)(b*Ln + t) * NPROJn + 512 + c;
    float acc = bc[c];
#pragma unroll
    for (int j = 0; j < 4; j++) {
        int tt = t + j - 3;
        if (tt >= 0) acc += g_proj[rbase + (size_t)(tt - t) * NPROJn] * Wc[c*4 + j];
    }
    float sg = 1.f / (1.f + expf(-acc));
    g_xbc[(size_t)(b*Ln + t) * CONVn + c] = acc * sg;
}

__global__ void dt_kernel(const float* __restrict__ dtb, const float* __restrict__ Alog) {
    int i = blockIdx.x * blockDim.x + threadIdx.x;
    if (i < 2*Ln*Hn) {
        int h = i & 7, row = i >> 3;
        float x = g_proj[(size_t)row*NPROJn + 1152 + h] + dtb[h];
        float dt = (x > 20.f) ? x : log1pf(expf(x));
        float A = -expf(Alog[h]);
        g_dt[i] = dt;
        g_dAr[i] = expf(dt * A);
    }
}

// ---------------- recurrent SSM scan ----------------
// grid 128 = b(2) x h(8) x dchunk(8), block 128 = dlocal(8) x sgroup(16, 4 s each)
__global__ __launch_bounds__(128) void scan_kernel() {
    int bx = blockIdx.x;
    int b = bx >> 6;
    int h = (bx >> 3) & 7;
    int dch = bx & 7;
    int tid = threadIdx.x;
    int dl = tid >> 4;
    int s0 = (tid & 15) * 4;
    int dg = dch * 8 + dl;

    __shared__ float sacc[16][132];

    const float* xbcb = g_xbc + (size_t)b * Ln * CONVn;
    const float* dAb = g_dAr + (size_t)b * Ln * Hn + h;
    const float* dtbp = g_dt + (size_t)b * Ln * Hn + h;

    float h0 = 0.f, h1 = 0.f, h2 = 0.f, h3 = 0.f;

    float4 Bp = *(const float4*)(xbcb + 512 + s0);
    float4 Cp = *(const float4*)(xbcb + 576 + s0);
    float xp = xbcb[h*64 + dg];
    float dAp = dAb[0], dtp = dtbp[0];

    for (int tile = 0; tile < Ln/16; ++tile) {
#pragma unroll
        for (int tt = 0; tt < 16; ++tt) {
            int t = tile * 16 + tt;
            float4 Bv = Bp; float4 Cv = Cp;
            float xv = xp, dA = dAp, dt = dtp;
            if (t + 1 < Ln) {
                const float* r = xbcb + (size_t)(t + 1) * CONVn;
                Bp = *(const float4*)(r + 512 + s0);
                Cp = *(const float4*)(r + 576 + s0);
                xp = r[h*64 + dg];
                dAp = dAb[(size_t)(t + 1) * Hn];
                dtp = dtbp[(size_t)(t + 1) * Hn];
            }
            float dtx = dt * xv;
            h0 = h0 * dA + dtx * Bv.x;
            h1 = h1 * dA + dtx * Bv.y;
            h2 = h2 * dA + dtx * Bv.z;
            h3 = h3 * dA + dtx * Bv.w;
            sacc[tt][tid] = h0*Cv.x + h1*Cv.y + h2*Cv.z + h3*Cv.w;
        }
        __syncthreads();
        int tt = tid >> 3, dd = tid & 7;
        float y = 0.f;
#pragma unroll
        for (int j = 0; j < 16; j++) y += sacc[tt][dd*16 + j];
        int t = tile * 16 + tt;
        g_ys[(size_t)(b*Ln + t) * DINn + h*64 + dch*8 + dd] = y;
        __syncthreads();
    }
}

// ---------------- y + D*x, silu(z) gate, gated RMSNorm ----------------
__global__ __launch_bounds__(128) void gated_kernel(
    const float* __restrict__ Dl, const float* __restrict__ rmsw)
{
    int row = blockIdx.x, tid = threadIdx.x;
    float gv[4]; float ss = 0.f;
#pragma unroll
    for (int e = 0; e < 4; e++) {
        int c = e * 128 + tid;
        int h = c >> 6;
        float ys = g_ys[(size_t)row*DINn + c];
        float xh = g_xbc[(size_t)row*CONVn + c];
        float z = g_proj[(size_t)row*NPROJn + c];
        float u = ys + Dl[h] * xh;
        float g = u * (z / (1.f + expf(-z)));
        gv[e] = g;
        ss += g * g;
    }
    float tot = blockSum<128>(ss);
    float r = rsqrtf(tot * (1.f/DINn) + 1e-5f);
#pragma unroll
    for (int e = 0; e < 4; e++) {
        int c = e * 128 + tid;
        g_gated[(size_t)row*DINn + c] = gv[e] * r * rmsw[c];
    }
}

// ---------------- unsort + mean + residual + LN (updates g_x) ----------------
__global__ __launch_bounds__(256) void combine_kernel() {
    int i = blockIdx.x, d = threadIdx.x;
    int i0 = g_inv[i];
    int i1 = g_inv[Qn + i];
    float v = g_x[(size_t)i*Dn + d]
            + 0.5f * (g_mo[(size_t)i0*Dn + d] + g_mo[(size_t)(Qn + i1)*Dn + d]);
    float mean = blockSum<256>(v) * (1.f/Dn);
    float c = v - mean;
    float var = blockSum<256>(c*c) * (1.f/Dn);
    g_x[(size_t)i*Dn + d] = c * rsqrtf(var + 1e-5f);
}

// ---------------- host ----------------
extern "C" void kernel_launch(void* const* d_in, const int* in_sizes, int n_in,
                              void* d_out, int out_size) {
    const float* query  = (const float*)d_in[0];
    const float* qpos   = (const float*)d_in[1];
    const float* feats  = (const float*)d_in[2];
    const float* spc    = (const float*)d_in[3];
    const float* w_q    = (const float*)d_in[4];
    const float* w_v    = (const float*)d_in[5];
    const float* w_o    = (const float*)d_in[6];
    const float* w_k    = (const float*)d_in[7];
    const float* w_b    = (const float*)d_in[8];
    const float* Win    = (const float*)d_in[9];
    const float* Wconv  = (const float*)d_in[10];
    const float* bconv  = (const float*)d_in[11];
    const float* Alog   = (const float*)d_in[12];
    const float* Dh     = (const float*)d_in[13];
    const float* dtbias = (const float*)d_in[14];
    const float* rmsw   = (const float*)d_in[15];
    const float* Wout   = (const float*)d_in[16];
    const float* fw1    = (const float*)d_in[17];
    const float* fb1    = (const float*)d_in[18];
    const float* fw2    = (const float*)d_in[19];
    const float* fb2    = (const float*)d_in[20];
    const int*   order  = (const int*)d_in[21];
    float* out = (float*)d_out;

    void *vq, *vfbar, *vvbar, *vwtmp, *vwo, *vx, *vxn, *vxs, *vproj, *vgated, *vmo, *vffnh, *vffno;
    cudaGetSymbolAddress(&vq, g_q);
    cudaGetSymbolAddress(&vfbar, g_fbar);
    cudaGetSymbolAddress(&vvbar, g_vbar);
    cudaGetSymbolAddress(&vwtmp, g_wtmp);
    cudaGetSymbolAddress(&vwo, g_wo);
    cudaGetSymbolAddress(&vx, g_x);
    cudaGetSymbolAddress(&vxn, g_xn);
    cudaGetSymbolAddress(&vxs, g_xs);
    cudaGetSymbolAddress(&vproj, g_proj);
    cudaGetSymbolAddress(&vgated, g_gated);
    cudaGetSymbolAddress(&vmo, g_mo);
    cudaGetSymbolAddress(&vffnh, g_ffnh);
    cudaGetSymbolAddress(&vffno, g_ffno);
    float* p_q = (float*)vq;       float* p_fbar = (float*)vfbar;
    float* p_vbar = (float*)vvbar; float* p_wtmp = (float*)vwtmp;
    float* p_wo = (float*)vwo;     float* p_x = (float*)vx;
    float* p_xn = (float*)vxn;     float* p_xs = (float*)vxs;
    float* p_proj = (float*)vproj; float* p_gated = (float*)vgated;
    float* p_mo = (float*)vmo;     float* p_ffnh = (float*)vffnh;
    float* p_ffno = (float*)vffno;

    dim3 gb(16, 16);

    // --- stage 1: KNN + aggregation ---
    pack_sp_kernel<<<Nn/256, 256>>>(spc);
    knn_kernel<<<Qn/16, 256>>>(qpos);
    gemm_kernel<<<dim3(Dn/64, Qn/64), gb>>>(query, w_q, nullptr, p_q, Qn, Dn, Dn, 0);
    kwfbar_kernel<<<Qn, 256>>>(w_k, w_b, feats);
    gemm_kernel<<<dim3(Dn/64, Qn/64), gb>>>(p_fbar, w_v, nullptr, p_vbar, Qn, Dn, Dn, 0);
    mul_kernel<<<(Qn*Dn)/256, 256>>>();
    gemm_kernel<<<dim3(Dn/64, Qn/64), gb>>>(p_wtmp, w_o, nullptr, p_wo, Qn, Dn, Dn, 0);
    ln_kernel<<<Qn, 256>>>(p_x, p_wo, query);

    inv_kernel<<<(2*Qn)/256, 256>>>(order);

    // --- stage 2: two Mamba2 SSM layers ---
    for (int l = 0; l < 2; l++) {
        const float* Win_l   = Win   + (size_t)l * NPROJn * Dn;
        const float* Wconv_l = Wconv + (size_t)l * CONVn * KCn;
        const float* bconv_l = bconv + (size_t)l * CONVn;
        const float* Alog_l  = Alog  + l * Hn;
        const float* D_l     = Dh    + l * Hn;
        const float* dtb_l   = dtbias+ l * Hn;
        const float* rmsw_l  = rmsw  + l * DINn;
        const float* Wout_l  = Wout  + (size_t)l * Dn * DINn;

        ln_kernel<<<Qn, 256>>>(p_xn, p_x, nullptr);
        gather_kernel<<<2*Qn, 256>>>(order);
        gemm_kernel<<<dim3((NPROJn+63)/64, (2*Qn)/64), gb>>>(p_xs, Win_l, nullptr, p_proj,
                                                             2*Qn, NPROJn, Dn, 0);
        conv_kernel<<<dim3(Ln, 2), CONVn>>>(Wconv_l, bconv_l);
        dt_kernel<<<(2*Ln*Hn)/256, 256>>>(dtb_l, Alog_l);
        scan_kernel<<<128, 128>>>();
        gated_kernel<<<2*Qn, 128>>>(D_l, rmsw_l);
        gemm_kernel<<<dim3(Dn/64, (2*Qn)/64), gb>>>(p_gated, Wout_l, nullptr, p_mo,
                                                    2*Qn, Dn, DINn, 0);
        combine_kernel<<<Qn, 256>>>();
    }

    // --- stage 3: FFN ---
    gemm_kernel<<<dim3(HIDn/64, Qn/64), gb>>>(p_x, fw1, fb1, p_ffnh, Qn, HIDn, Dn, 1);
    gemm_kernel<<<dim3(Dn/64, Qn/64), gb>>>(p_ffnh, fw2, fb2, p_ffno, Qn, Dn, HIDn, 0);
    ln_kernel<<<Qn, 256>>>(out, p_ffno, p_x);
}